// round 3
// baseline (speedup 1.0000x reference)
#include <cuda_runtime.h>
#include <cuda_bf16.h>

// ---------------- problem constants ----------------
#define BAG  8
#define SEQ  512
#define DIM  768
#define NPD  6
#define NN_  48          // N nodes
#define TT   2304        // T = N*N
#define NHEAD 8
#define DK   96
#define DFF  1024
#define NLAYER 4
#define NREL 97

// ---------------- device scratch (no allocations allowed) ----------------
__device__ float g_htb [NN_ * DIM];
__device__ float g_u   [NN_ * DIM];
__device__ float g_v   [NN_ * DIM];
__device__ float g_x   [TT * DIM];
__device__ float g_q   [TT * DIM];
__device__ float g_k   [TT * DIM];
__device__ float g_vv  [TT * DIM];
__device__ float g_attn[TT * DIM];
__device__ float g_tmp [TT * DIM];
__device__ float g_ffn [TT * DFF];
__device__ float g_S   [(size_t)NHEAD * TT * TT];   // 170 MB attention scores
__device__ float g_ht  [BAG * NREL];

// ---------------- block reduction helper ----------------
__device__ __forceinline__ float blk_reduce(float val, float* sh, bool do_max) {
    const unsigned mask = 0xffffffffu;
#pragma unroll
    for (int o = 16; o > 0; o >>= 1) {
        float other = __shfl_xor_sync(mask, val, o);
        val = do_max ? fmaxf(val, other) : (val + other);
    }
    int lane = threadIdx.x & 31, w = threadIdx.x >> 5;
    __syncthreads();
    if (lane == 0) sh[w] = val;
    __syncthreads();
    int nw = (blockDim.x + 31) >> 5;
    if (w == 0) {
        val = (lane < nw) ? sh[lane] : (do_max ? -3.4e38f : 0.f);
#pragma unroll
        for (int o = 16; o > 0; o >>= 1) {
            float other = __shfl_xor_sync(mask, val, o);
            val = do_max ? fmaxf(val, other) : (val + other);
        }
        if (lane == 0) sh[0] = val;
    }
    __syncthreads();
    return sh[0];
}

// ---------------- generic tiled SGEMM ----------------
// C[m,n] = sum_k A[m,k] * (TRANSB ? B[n,k] : B[k,n])  (+bias) (ReLU)
// batched over blockIdx.z with element strides.
template<bool TRANSB, bool BIAS, bool RELU>
__global__ void gemm_kernel(const float* __restrict__ A, const float* __restrict__ B,
                            const float* __restrict__ bias, float* __restrict__ C,
                            int M, int N, int K, int lda, int ldb, int ldc,
                            long strideA, long strideB, long strideC)
{
    constexpr int BM = 64, BN = 64, BK = 16, TM = 4, TN = 4;
    A += (long)blockIdx.z * strideA;
    B += (long)blockIdx.z * strideB;
    C += (long)blockIdx.z * strideC;

    __shared__ float As[BK][BM + 4];
    __shared__ float Bs[BK][BN + 4];

    const int row0 = blockIdx.y * BM;
    const int col0 = blockIdx.x * BN;
    const int tid  = threadIdx.x;
    const int tr   = tid >> 4;    // 0..15
    const int tc   = tid & 15;    // 0..15

    float acc[TM][TN];
#pragma unroll
    for (int i = 0; i < TM; i++)
#pragma unroll
        for (int j = 0; j < TN; j++) acc[i][j] = 0.f;

    for (int k0 = 0; k0 < K; k0 += BK) {
        // load A tile (BM x BK)
#pragma unroll
        for (int it = 0; it < (BM * BK) / 256; it++) {
            int i = tid + it * 256;
            int m = i >> 4, k = i & 15;
            int gm = row0 + m, gk = k0 + k;
            As[k][m] = (gm < M && gk < K) ? A[(long)gm * lda + gk] : 0.f;
        }
        // load B tile
#pragma unroll
        for (int it = 0; it < (BK * BN) / 256; it++) {
            int i = tid + it * 256;
            if (TRANSB) {
                int n = i >> 4, k = i & 15;
                int gn = col0 + n, gk = k0 + k;
                Bs[k][n] = (gn < N && gk < K) ? B[(long)gn * ldb + gk] : 0.f;
            } else {
                int k = i >> 6, n = i & 63;
                int gk = k0 + k, gn = col0 + n;
                Bs[k][n] = (gk < K && gn < N) ? B[(long)gk * ldb + gn] : 0.f;
            }
        }
        __syncthreads();
#pragma unroll
        for (int k = 0; k < BK; k++) {
            float4 a4 = *reinterpret_cast<const float4*>(&As[k][tr * TM]);
            float4 b4 = *reinterpret_cast<const float4*>(&Bs[k][tc * TN]);
            float a[TM] = {a4.x, a4.y, a4.z, a4.w};
            float b[TN] = {b4.x, b4.y, b4.z, b4.w};
#pragma unroll
            for (int i = 0; i < TM; i++)
#pragma unroll
                for (int j = 0; j < TN; j++)
                    acc[i][j] = fmaf(a[i], b[j], acc[i][j]);
        }
        __syncthreads();
    }

#pragma unroll
    for (int i = 0; i < TM; i++) {
        int gm = row0 + tr * TM + i;
        if (gm >= M) continue;
#pragma unroll
        for (int j = 0; j < TN; j++) {
            int gn = col0 + tc * TN + j;
            if (gn >= N) continue;
            float v = acc[i][j];
            if (BIAS) v += bias[gn];
            if (RELU) v = fmaxf(v, 0.f);
            C[(long)gm * ldc + gn] = v;
        }
    }
}

// ---------------- span max pooling ----------------
__global__ void pool_kernel(const float* __restrict__ emb, const int* __restrict__ spans,
                            float* __restrict__ htb)
{
    int node = blockIdx.x;                 // 0..47
    int bag  = node / NPD;
    int s0 = spans[node * 2 + 0];
    int s1 = spans[node * 2 + 1];
    const float* base = emb + (long)bag * SEQ * DIM;
    for (int d = threadIdx.x; d < DIM; d += blockDim.x) {
        float m = -3.4e38f;
        for (int p = s0; p <= s1; p++)
            m = fmaxf(m, base[(long)p * DIM + d]);
        htb[(long)node * DIM + d] = m;
    }
}

// ---------------- pairwise relu(u_i + v_j) ----------------
__global__ void build_pair_kernel(const float* __restrict__ u, const float* __restrict__ v,
                                  float* __restrict__ out)
{
    int t = blockIdx.x;         // 0..2303
    int i = t / NN_, j = t % NN_;
    const float* ur = u + (long)i * DIM;
    const float* vr = v + (long)j * DIM;
    float* o = out + (long)t * DIM;
#pragma unroll
    for (int it = 0; it < DIM / 256; it++) {
        int d = threadIdx.x + it * 256;
        o[d] = fmaxf(ur[d] + vr[d], 0.f);
    }
}

// ---------------- softmax over score rows (scale fused) ----------------
__global__ void softmax_kernel(float* __restrict__ S, float scale)
{
    long base = ((long)blockIdx.y * TT + blockIdx.x) * TT;
    float* row = S + base;
    __shared__ float sh[32];
    float v[9];
    float m = -3.4e38f;
#pragma unroll
    for (int i = 0; i < 9; i++) {
        v[i] = row[threadIdx.x + i * 256] * scale;
        m = fmaxf(m, v[i]);
    }
    m = blk_reduce(m, sh, true);
    float s = 0.f;
#pragma unroll
    for (int i = 0; i < 9; i++) {
        v[i] = __expf(v[i] - m);
        s += v[i];
    }
    s = blk_reduce(s, sh, false);
    float inv = 1.f / s;
#pragma unroll
    for (int i = 0; i < 9; i++)
        row[threadIdx.x + i * 256] = v[i] * inv;
}

// ---------------- x = LN(x + o) * g + b ----------------
__global__ void add_ln_kernel(float* __restrict__ x, const float* __restrict__ o,
                              const float* __restrict__ g, const float* __restrict__ b)
{
    long base = (long)blockIdx.x * DIM;
    float* xr = x + base;
    const float* orr = o + base;
    __shared__ float sh[32];
    float v[3];
    float s = 0.f, s2 = 0.f;
#pragma unroll
    for (int i = 0; i < 3; i++) {
        int d = threadIdx.x + i * 256;
        float t = xr[d] + orr[d];
        v[i] = t; s += t; s2 += t * t;
    }
    s  = blk_reduce(s,  sh, false);
    s2 = blk_reduce(s2, sh, false);
    float mean = s * (1.f / DIM);
    float var  = s2 * (1.f / DIM) - mean * mean;
    float inv  = rsqrtf(var + 1e-5f);
#pragma unroll
    for (int i = 0; i < 3; i++) {
        int d = threadIdx.x + i * 256;
        xr[d] = (v[i] - mean) * inv * g[d] + b[d];
    }
}

// ---------------- final: gather (h,t) cells, LN, predictor ----------------
__global__ void final_kernel(const float* __restrict__ x, const float* __restrict__ ng,
                             const float* __restrict__ nb, const float* __restrict__ Wp,
                             const float* __restrict__ bp, float* __restrict__ ht)
{
    int bag = blockIdx.x;
    long r = (long)(bag * NPD) * NN_ + (bag * NPD + 1);
    const float* row = x + r * DIM;
    __shared__ float sh[DIM];
    __shared__ float red[32];
    float s = 0.f, s2 = 0.f;
    for (int d = threadIdx.x; d < DIM; d += blockDim.x) {
        float t = row[d];
        sh[d] = t; s += t; s2 += t * t;
    }
    s  = blk_reduce(s,  red, false);
    s2 = blk_reduce(s2, red, false);
    float mean = s * (1.f / DIM);
    float inv  = rsqrtf(s2 * (1.f / DIM) - mean * mean + 1e-5f);
    __syncthreads();
    for (int d = threadIdx.x; d < DIM; d += blockDim.x)
        sh[d] = (sh[d] - mean) * inv * ng[d] + nb[d];
    __syncthreads();
    for (int n = threadIdx.x; n < NREL; n += blockDim.x) {
        float acc = bp[n];
        for (int k = 0; k < DIM; k++)
            acc = fmaf(sh[k], Wp[(long)k * NREL + n], acc);
        ht[bag * NREL + n] = acc;
    }
}

// ---------------- output assembly: bag max + layout ----------------
__global__ void writeout_kernel(const float* __restrict__ ht, float* __restrict__ out,
                                int out_size)
{
    int n = threadIdx.x;
    if (n >= NREL) return;
    float m = -3.4e38f;
    for (int b = 0; b < BAG; b++) m = fmaxf(m, ht[b * NREL + n]);
    if (out_size >= NREL * (BAG + 1)) {
        out[n] = m;
        for (int b = 0; b < BAG; b++) out[NREL + b * NREL + n] = ht[b * NREL + n];
    } else if (out_size == NREL) {
        out[n] = m;
    } else {
        for (int b = 0; b < BAG; b++) out[b * NREL + n] = ht[b * NREL + n];
    }
}

// ---------------- host ----------------
static inline dim3 gemm_grid(int M, int N, int Z) {
    return dim3((unsigned)((N + 63) / 64), (unsigned)((M + 63) / 64), (unsigned)Z);
}

template <typename T>
static inline float* sym(T& s) {
    void* p = nullptr;
    cudaGetSymbolAddress(&p, s);
    return (float*)p;
}

extern "C" void kernel_launch(void* const* d_in, const int* in_sizes, int n_in,
                              void* d_out, int out_size)
{
    const float* emb   = (const float*)d_in[0];
    const int*   spans = (const int*)  d_in[1];
    const float* Wu = (const float*)d_in[2];  const float* bu = (const float*)d_in[3];
    const float* Wv = (const float*)d_in[4];  const float* bv = (const float*)d_in[5];
    const float* Wl = (const float*)d_in[6];  const float* bl = (const float*)d_in[7];
    const float* Wq = (const float*)d_in[8];  const float* bq = (const float*)d_in[9];
    const float* Wk = (const float*)d_in[10]; const float* bk = (const float*)d_in[11];
    const float* Wvm= (const float*)d_in[12]; const float* bvm= (const float*)d_in[13];
    const float* Wo = (const float*)d_in[14]; const float* bo = (const float*)d_in[15];
    const float* F1 = (const float*)d_in[16]; const float* f1 = (const float*)d_in[17];
    const float* F2 = (const float*)d_in[18]; const float* f2 = (const float*)d_in[19];
    const float* g1 = (const float*)d_in[20]; const float* be1= (const float*)d_in[21];
    const float* g2 = (const float*)d_in[22]; const float* be2= (const float*)d_in[23];
    const float* ng = (const float*)d_in[24]; const float* nb = (const float*)d_in[25];
    const float* Wp = (const float*)d_in[26]; const float* bp = (const float*)d_in[27];

    float* htb = sym(g_htb);
    float* u   = sym(g_u);
    float* v   = sym(g_v);
    float* x   = sym(g_x);
    float* q   = sym(g_q);
    float* k   = sym(g_k);
    float* vv  = sym(g_vv);
    float* attn= sym(g_attn);
    float* tmp = sym(g_tmp);
    float* ffn = sym(g_ffn);
    float* S   = sym(g_S);
    float* ht  = sym(g_ht);
    float* out = (float*)d_out;

    const float scale = 0.102062072615966f;   // 1/sqrt(96)

    // 1) span max pooling -> htb [48,768]
    pool_kernel<<<NN_, 256>>>(emb, spans, htb);

    // 2) u = htb@Wu+bu ; v = htb@Wv+bv
    gemm_kernel<false,true,false><<<gemm_grid(NN_, DIM, 1), 256>>>(
        htb, Wu, bu, u, NN_, DIM, DIM, DIM, DIM, DIM, 0, 0, 0);
    gemm_kernel<false,true,false><<<gemm_grid(NN_, DIM, 1), 256>>>(
        htb, Wv, bv, v, NN_, DIM, DIM, DIM, DIM, DIM, 0, 0, 0);

    // 3) pair = relu(u_i + v_j) ; x = relu(pair @ Wl + bl)
    build_pair_kernel<<<TT, 256>>>(u, v, tmp);
    gemm_kernel<false,true,true><<<gemm_grid(TT, DIM, 1), 256>>>(
        tmp, Wl, bl, x, TT, DIM, DIM, DIM, DIM, DIM, 0, 0, 0);

    // 4) MatTransformer layers
    for (int l = 0; l < NLAYER; l++) {
        const float* Wq_l = Wq + (size_t)l * DIM * DIM;  const float* bq_l = bq + (size_t)l * DIM;
        const float* Wk_l = Wk + (size_t)l * DIM * DIM;  const float* bk_l = bk + (size_t)l * DIM;
        const float* Wv_l = Wvm+ (size_t)l * DIM * DIM;  const float* bv_l = bvm+ (size_t)l * DIM;
        const float* Wo_l = Wo + (size_t)l * DIM * DIM;  const float* bo_l = bo + (size_t)l * DIM;
        const float* F1_l = F1 + (size_t)l * DIM * DFF;  const float* f1_l = f1 + (size_t)l * DFF;
        const float* F2_l = F2 + (size_t)l * DFF * DIM;  const float* f2_l = f2 + (size_t)l * DIM;
        const float* g1_l = g1 + (size_t)l * DIM;        const float* be1_l= be1+ (size_t)l * DIM;
        const float* g2_l = g2 + (size_t)l * DIM;        const float* be2_l= be2+ (size_t)l * DIM;

        // QKV projections
        gemm_kernel<false,true,false><<<gemm_grid(TT, DIM, 1), 256>>>(
            x, Wq_l, bq_l, q, TT, DIM, DIM, DIM, DIM, DIM, 0, 0, 0);
        gemm_kernel<false,true,false><<<gemm_grid(TT, DIM, 1), 256>>>(
            x, Wk_l, bk_l, k, TT, DIM, DIM, DIM, DIM, DIM, 0, 0, 0);
        gemm_kernel<false,true,false><<<gemm_grid(TT, DIM, 1), 256>>>(
            x, Wv_l, bv_l, vv, TT, DIM, DIM, DIM, DIM, DIM, 0, 0, 0);

        // scores: S[h] = Q_h @ K_h^T (batched over heads via z, head offset = h*96)
        gemm_kernel<true,false,false><<<gemm_grid(TT, TT, NHEAD), 256>>>(
            q, k, nullptr, S, TT, TT, DK, DIM, DIM, TT,
            (long)DK, (long)DK, (long)TT * TT);

        // softmax (scale fused)
        softmax_kernel<<<dim3(TT, NHEAD), 256>>>(S, scale);

        // attn_h = S[h] @ V_h
        gemm_kernel<false,false,false><<<gemm_grid(TT, DK, NHEAD), 256>>>(
            S, vv, nullptr, attn, TT, DK, TT, TT, DIM, DIM,
            (long)TT * TT, (long)DK, (long)DK);

        // output projection + residual LN
        gemm_kernel<false,true,false><<<gemm_grid(TT, DIM, 1), 256>>>(
            attn, Wo_l, bo_l, tmp, TT, DIM, DIM, DIM, DIM, DIM, 0, 0, 0);
        add_ln_kernel<<<TT, 256>>>(x, tmp, g1_l, be1_l);

        // FFN + residual LN
        gemm_kernel<false,true,true><<<gemm_grid(TT, DFF, 1), 256>>>(
            x, F1_l, f1_l, ffn, TT, DFF, DIM, DIM, DFF, DFF, 0, 0, 0);
        gemm_kernel<false,true,false><<<gemm_grid(TT, DIM, 1), 256>>>(
            ffn, F2_l, f2_l, tmp, TT, DIM, DFF, DFF, DIM, DIM, 0, 0, 0);
        add_ln_kernel<<<TT, 256>>>(x, tmp, g2_l, be2_l);
    }

    // 5) final gather + LN + predictor + bag max
    final_kernel<<<BAG, 256>>>(x, ng, nb, Wp, bp, ht);
    writeout_kernel<<<1, 128>>>(ht, out, out_size);
}

// round 4
// speedup vs baseline: 1.0124x; 1.0124x over previous
#include <cuda_runtime.h>
#include <cuda_bf16.h>

// ---------------- problem constants ----------------
#define BAG  8
#define SEQ  512
#define DIM  768
#define NPD  6
#define NN_  48          // N nodes
#define TT   2304        // T = N*N
#define NHEAD 8
#define DK   96
#define DFF  1024
#define NLAYER 4
#define NREL 97

typedef unsigned long long u64;

// ---------------- f32x2 packed-math helpers (sm_100+ FFMA2 path) ----------------
__device__ __forceinline__ u64 dup_f32x2(float a) {
    u64 r; asm("mov.b64 %0, {%1, %1};" : "=l"(r) : "f"(a)); return r;
}
__device__ __forceinline__ void fma_f32x2(u64& d, u64 a, u64 b) {
    asm("fma.rn.f32x2 %0, %1, %2, %0;" : "+l"(d) : "l"(a), "l"(b));
}
__device__ __forceinline__ void unpack_f32x2(u64 v, float& lo, float& hi) {
    asm("mov.b64 {%0, %1}, %2;" : "=f"(lo), "=f"(hi) : "l"(v));
}

// ---------------- device scratch (no allocations allowed) ----------------
__device__ float g_htb [NN_ * DIM];
__device__ float g_u   [NN_ * DIM];
__device__ float g_v   [NN_ * DIM];
__device__ float g_x   [TT * DIM];
__device__ float g_q   [TT * DIM];
__device__ float g_k   [TT * DIM];
__device__ float g_vv  [TT * DIM];
__device__ float g_attn[TT * DIM];
__device__ float g_tmp [TT * DIM];
__device__ float g_ffn [TT * DFF];
__device__ float g_S   [(size_t)NHEAD * TT * TT];   // 170 MB attention scores
__device__ float g_ht  [BAG * NREL];

// ---------------- block reduction helper ----------------
__device__ __forceinline__ float blk_reduce(float val, float* sh, bool do_max) {
    const unsigned mask = 0xffffffffu;
#pragma unroll
    for (int o = 16; o > 0; o >>= 1) {
        float other = __shfl_xor_sync(mask, val, o);
        val = do_max ? fmaxf(val, other) : (val + other);
    }
    int lane = threadIdx.x & 31, w = threadIdx.x >> 5;
    __syncthreads();
    if (lane == 0) sh[w] = val;
    __syncthreads();
    int nw = (blockDim.x + 31) >> 5;
    if (w == 0) {
        val = (lane < nw) ? sh[lane] : (do_max ? -3.4e38f : 0.f);
#pragma unroll
        for (int o = 16; o > 0; o >>= 1) {
            float other = __shfl_xor_sync(mask, val, o);
            val = do_max ? fmaxf(val, other) : (val + other);
        }
        if (lane == 0) sh[0] = val;
    }
    __syncthreads();
    return sh[0];
}

// ---------------- 128x128 double-buffered SGEMM with f32x2 FMA ----------------
// C[m,n] = sum_k A[m,k] * (TRANSB ? B[n,k] : B[k,n])  (+bias) (ReLU)
// Requires: K % 16 == 0, N % 4 == 0, lda/ldb/ldc % 4 == 0 (true for all calls).
template<bool TRANSB, bool BIAS, bool RELU>
__global__ __launch_bounds__(256)
void gemm128(const float* __restrict__ A, const float* __restrict__ B,
             const float* __restrict__ bias, float* __restrict__ C,
             int M, int N, int K, int lda, int ldb, int ldc,
             long sA, long sB, long sC)
{
    constexpr int BM = 128, BN = 128, BK = 16, LDS_ = BM + 4;  // PAD=4
    A += (long)blockIdx.z * sA;
    B += (long)blockIdx.z * sB;
    C += (long)blockIdx.z * sC;

    __shared__ float As[2][BK][LDS_];
    __shared__ float Bs[2][BK][LDS_];

    const int tid  = threadIdx.x;
    const int row0 = blockIdx.y * BM;
    const int col0 = blockIdx.x * BN;
    const int tx   = tid & 15;
    const int ty   = tid >> 4;

    // A-tile load mapping: float4 along k, two rows (m, m+64) per thread
    const int ma = tid >> 2;
    const int ka = (tid & 3) * 4;
    // B-tile load mapping
    const int nb  = tid >> 2;          // TRANSB: row within tile
    const int kb  = (tid & 3) * 4;     // TRANSB: k offset
    const int bk0 = tid >> 5;          // non-trans: k row
    const int bn4 = (tid & 31) * 4;    // non-trans: n offset

    const float4 f4z = make_float4(0.f, 0.f, 0.f, 0.f);
    float4 ra0, ra1, rb0, rb1;

    u64 acc[8][4];
#pragma unroll
    for (int i = 0; i < 8; i++)
#pragma unroll
        for (int j = 0; j < 4; j++) acc[i][j] = 0ull;

    const int KT = K / BK;

    // ---- fetch tile kt into registers ----
    auto fetch = [&](int k0) {
        int gm0 = row0 + ma, gm1 = gm0 + 64;
        ra0 = (gm0 < M) ? *(const float4*)(A + (long)gm0 * lda + k0 + ka) : f4z;
        ra1 = (gm1 < M) ? *(const float4*)(A + (long)gm1 * lda + k0 + ka) : f4z;
        if (TRANSB) {
            int gn0 = col0 + nb, gn1 = gn0 + 64;
            rb0 = (gn0 < N) ? *(const float4*)(B + (long)gn0 * ldb + k0 + kb) : f4z;
            rb1 = (gn1 < N) ? *(const float4*)(B + (long)gn1 * ldb + k0 + kb) : f4z;
        } else {
            int gn = col0 + bn4;
            rb0 = (gn < N) ? *(const float4*)(B + (long)(k0 + bk0) * ldb + gn) : f4z;
            rb1 = (gn < N) ? *(const float4*)(B + (long)(k0 + bk0 + 8) * ldb + gn) : f4z;
        }
    };
    // ---- store registers into smem buffer ----
    auto stage = [&](int buf) {
        As[buf][ka + 0][ma]      = ra0.x; As[buf][ka + 1][ma]      = ra0.y;
        As[buf][ka + 2][ma]      = ra0.z; As[buf][ka + 3][ma]      = ra0.w;
        As[buf][ka + 0][ma + 64] = ra1.x; As[buf][ka + 1][ma + 64] = ra1.y;
        As[buf][ka + 2][ma + 64] = ra1.z; As[buf][ka + 3][ma + 64] = ra1.w;
        if (TRANSB) {
            Bs[buf][kb + 0][nb]      = rb0.x; Bs[buf][kb + 1][nb]      = rb0.y;
            Bs[buf][kb + 2][nb]      = rb0.z; Bs[buf][kb + 3][nb]      = rb0.w;
            Bs[buf][kb + 0][nb + 64] = rb1.x; Bs[buf][kb + 1][nb + 64] = rb1.y;
            Bs[buf][kb + 2][nb + 64] = rb1.z; Bs[buf][kb + 3][nb + 64] = rb1.w;
        } else {
            *(float4*)&Bs[buf][bk0][bn4]     = rb0;
            *(float4*)&Bs[buf][bk0 + 8][bn4] = rb1;
        }
    };

    fetch(0);
    stage(0);
    __syncthreads();

    for (int kt = 0; kt < KT; kt++) {
        const int cur = kt & 1;
        const bool hn = (kt + 1 < KT);
        if (hn) fetch((kt + 1) * BK);

#pragma unroll
        for (int k = 0; k < BK; k++) {
            float4 a0 = *(const float4*)&As[cur][k][ty * 8];
            float4 a1 = *(const float4*)&As[cur][k][ty * 8 + 4];
            ulonglong2 p0 = *(const ulonglong2*)&Bs[cur][k][tx * 8];
            ulonglong2 p1 = *(const ulonglong2*)&Bs[cur][k][tx * 8 + 4];
            u64 bq[4] = {p0.x, p0.y, p1.x, p1.y};
            float av[8] = {a0.x, a0.y, a0.z, a0.w, a1.x, a1.y, a1.z, a1.w};
#pragma unroll
            for (int i = 0; i < 8; i++) {
                u64 ad = dup_f32x2(av[i]);
#pragma unroll
                for (int j = 0; j < 4; j++) fma_f32x2(acc[i][j], ad, bq[j]);
            }
        }

        if (hn) stage(cur ^ 1);
        __syncthreads();
    }

    // ---- epilogue ----
    float bv[8];
    if (BIAS) {
#pragma unroll
        for (int j = 0; j < 8; j++) {
            int gn = col0 + tx * 8 + j;
            bv[j] = (gn < N) ? bias[gn] : 0.f;
        }
    }
#pragma unroll
    for (int i = 0; i < 8; i++) {
        int gm = row0 + ty * 8 + i;
        if (gm >= M) continue;
        float o[8];
#pragma unroll
        for (int j = 0; j < 4; j++) unpack_f32x2(acc[i][j], o[2 * j], o[2 * j + 1]);
        if (BIAS) {
#pragma unroll
            for (int j = 0; j < 8; j++) o[j] += bv[j];
        }
        if (RELU) {
#pragma unroll
            for (int j = 0; j < 8; j++) o[j] = fmaxf(o[j], 0.f);
        }
        int gn0 = col0 + tx * 8;
        float* crow = C + (long)gm * ldc;
        if (gn0 < N)     *(float4*)(crow + gn0)     = make_float4(o[0], o[1], o[2], o[3]);
        if (gn0 + 4 < N) *(float4*)(crow + gn0 + 4) = make_float4(o[4], o[5], o[6], o[7]);
    }
}

// ---------------- span max pooling ----------------
__global__ void pool_kernel(const float* __restrict__ emb, const int* __restrict__ spans,
                            float* __restrict__ htb)
{
    int node = blockIdx.x;                 // 0..47
    int bag  = node / NPD;
    int s0 = spans[node * 2 + 0];
    int s1 = spans[node * 2 + 1];
    const float* base = emb + (long)bag * SEQ * DIM;
    for (int d = threadIdx.x; d < DIM; d += blockDim.x) {
        float m = -3.4e38f;
        for (int p = s0; p <= s1; p++)
            m = fmaxf(m, base[(long)p * DIM + d]);
        htb[(long)node * DIM + d] = m;
    }
}

// ---------------- pairwise relu(u_i + v_j) ----------------
__global__ void build_pair_kernel(const float* __restrict__ u, const float* __restrict__ v,
                                  float* __restrict__ out)
{
    int t = blockIdx.x;         // 0..2303
    int i = t / NN_, j = t % NN_;
    const float* ur = u + (long)i * DIM;
    const float* vr = v + (long)j * DIM;
    float* o = out + (long)t * DIM;
#pragma unroll
    for (int it = 0; it < DIM / 256; it++) {
        int d = threadIdx.x + it * 256;
        o[d] = fmaxf(ur[d] + vr[d], 0.f);
    }
}

// ---------------- softmax over score rows (scale fused) ----------------
__global__ void softmax_kernel(float* __restrict__ S, float scale)
{
    long base = ((long)blockIdx.y * TT + blockIdx.x) * TT;
    float* row = S + base;
    __shared__ float sh[32];
    float v[9];
    float m = -3.4e38f;
#pragma unroll
    for (int i = 0; i < 9; i++) {
        v[i] = row[threadIdx.x + i * 256] * scale;
        m = fmaxf(m, v[i]);
    }
    m = blk_reduce(m, sh, true);
    float s = 0.f;
#pragma unroll
    for (int i = 0; i < 9; i++) {
        v[i] = __expf(v[i] - m);
        s += v[i];
    }
    s = blk_reduce(s, sh, false);
    float inv = 1.f / s;
#pragma unroll
    for (int i = 0; i < 9; i++)
        row[threadIdx.x + i * 256] = v[i] * inv;
}

// ---------------- x = LN(x + o) * g + b ----------------
__global__ void add_ln_kernel(float* __restrict__ x, const float* __restrict__ o,
                              const float* __restrict__ g, const float* __restrict__ b)
{
    long base = (long)blockIdx.x * DIM;
    float* xr = x + base;
    const float* orr = o + base;
    __shared__ float sh[32];
    float v[3];
    float s = 0.f, s2 = 0.f;
#pragma unroll
    for (int i = 0; i < 3; i++) {
        int d = threadIdx.x + i * 256;
        float t = xr[d] + orr[d];
        v[i] = t; s += t; s2 += t * t;
    }
    s  = blk_reduce(s,  sh, false);
    s2 = blk_reduce(s2, sh, false);
    float mean = s * (1.f / DIM);
    float var  = s2 * (1.f / DIM) - mean * mean;
    float inv  = rsqrtf(var + 1e-5f);
#pragma unroll
    for (int i = 0; i < 3; i++) {
        int d = threadIdx.x + i * 256;
        xr[d] = (v[i] - mean) * inv * g[d] + b[d];
    }
}

// ---------------- final: gather (h,t) cells, LN, predictor ----------------
__global__ void final_kernel(const float* __restrict__ x, const float* __restrict__ ng,
                             const float* __restrict__ nb, const float* __restrict__ Wp,
                             const float* __restrict__ bp, float* __restrict__ ht)
{
    int bag = blockIdx.x;
    long r = (long)(bag * NPD) * NN_ + (bag * NPD + 1);
    const float* row = x + r * DIM;
    __shared__ float sh[DIM];
    __shared__ float red[32];
    float s = 0.f, s2 = 0.f;
    for (int d = threadIdx.x; d < DIM; d += blockDim.x) {
        float t = row[d];
        sh[d] = t; s += t; s2 += t * t;
    }
    s  = blk_reduce(s,  red, false);
    s2 = blk_reduce(s2, red, false);
    float mean = s * (1.f / DIM);
    float inv  = rsqrtf(s2 * (1.f / DIM) - mean * mean + 1e-5f);
    __syncthreads();
    for (int d = threadIdx.x; d < DIM; d += blockDim.x)
        sh[d] = (sh[d] - mean) * inv * ng[d] + nb[d];
    __syncthreads();
    for (int n = threadIdx.x; n < NREL; n += blockDim.x) {
        float acc = bp[n];
        for (int k = 0; k < DIM; k++)
            acc = fmaf(sh[k], Wp[(long)k * NREL + n], acc);
        ht[bag * NREL + n] = acc;
    }
}

// ---------------- output assembly: bag max + layout ----------------
__global__ void writeout_kernel(const float* __restrict__ ht, float* __restrict__ out,
                                int out_size)
{
    int n = threadIdx.x;
    if (n >= NREL) return;
    float m = -3.4e38f;
    for (int b = 0; b < BAG; b++) m = fmaxf(m, ht[b * NREL + n]);
    if (out_size >= NREL * (BAG + 1)) {
        out[n] = m;
        for (int b = 0; b < BAG; b++) out[NREL + b * NREL + n] = ht[b * NREL + n];
    } else if (out_size == NREL) {
        out[n] = m;
    } else {
        for (int b = 0; b < BAG; b++) out[b * NREL + n] = ht[b * NREL + n];
    }
}

// ---------------- host ----------------
static inline dim3 gemm_grid(int M, int N, int Z) {
    return dim3((unsigned)((N + 127) / 128), (unsigned)((M + 127) / 128), (unsigned)Z);
}

template <typename T>
static inline float* sym(T& s) {
    void* p = nullptr;
    cudaGetSymbolAddress(&p, s);
    return (float*)p;
}

extern "C" void kernel_launch(void* const* d_in, const int* in_sizes, int n_in,
                              void* d_out, int out_size)
{
    const float* emb   = (const float*)d_in[0];
    const int*   spans = (const int*)  d_in[1];
    const float* Wu = (const float*)d_in[2];  const float* bu = (const float*)d_in[3];
    const float* Wv = (const float*)d_in[4];  const float* bv = (const float*)d_in[5];
    const float* Wl = (const float*)d_in[6];  const float* bl = (const float*)d_in[7];
    const float* Wq = (const float*)d_in[8];  const float* bq = (const float*)d_in[9];
    const float* Wk = (const float*)d_in[10]; const float* bk = (const float*)d_in[11];
    const float* Wvm= (const float*)d_in[12]; const float* bvm= (const float*)d_in[13];
    const float* Wo = (const float*)d_in[14]; const float* bo = (const float*)d_in[15];
    const float* F1 = (const float*)d_in[16]; const float* f1 = (const float*)d_in[17];
    const float* F2 = (const float*)d_in[18]; const float* f2 = (const float*)d_in[19];
    const float* g1 = (const float*)d_in[20]; const float* be1= (const float*)d_in[21];
    const float* g2 = (const float*)d_in[22]; const float* be2= (const float*)d_in[23];
    const float* ng = (const float*)d_in[24]; const float* nb = (const float*)d_in[25];
    const float* Wp = (const float*)d_in[26]; const float* bp = (const float*)d_in[27];

    float* htb = sym(g_htb);
    float* u   = sym(g_u);
    float* v   = sym(g_v);
    float* x   = sym(g_x);
    float* q   = sym(g_q);
    float* k   = sym(g_k);
    float* vv  = sym(g_vv);
    float* attn= sym(g_attn);
    float* tmp = sym(g_tmp);
    float* ffn = sym(g_ffn);
    float* S   = sym(g_S);
    float* ht  = sym(g_ht);
    float* out = (float*)d_out;

    const float scale = 0.102062072615966f;   // 1/sqrt(96)

    // 1) span max pooling -> htb [48,768]
    pool_kernel<<<NN_, 256>>>(emb, spans, htb);

    // 2) u = htb@Wu+bu ; v = htb@Wv+bv
    gemm128<false,true,false><<<gemm_grid(NN_, DIM, 1), 256>>>(
        htb, Wu, bu, u, NN_, DIM, DIM, DIM, DIM, DIM, 0, 0, 0);
    gemm128<false,true,false><<<gemm_grid(NN_, DIM, 1), 256>>>(
        htb, Wv, bv, v, NN_, DIM, DIM, DIM, DIM, DIM, 0, 0, 0);

    // 3) pair = relu(u_i + v_j) ; x = relu(pair @ Wl + bl)
    build_pair_kernel<<<TT, 256>>>(u, v, tmp);
    gemm128<false,true,true><<<gemm_grid(TT, DIM, 1), 256>>>(
        tmp, Wl, bl, x, TT, DIM, DIM, DIM, DIM, DIM, 0, 0, 0);

    // 4) MatTransformer layers
    for (int l = 0; l < NLAYER; l++) {
        const float* Wq_l = Wq + (size_t)l * DIM * DIM;  const float* bq_l = bq + (size_t)l * DIM;
        const float* Wk_l = Wk + (size_t)l * DIM * DIM;  const float* bk_l = bk + (size_t)l * DIM;
        const float* Wv_l = Wvm+ (size_t)l * DIM * DIM;  const float* bv_l = bvm+ (size_t)l * DIM;
        const float* Wo_l = Wo + (size_t)l * DIM * DIM;  const float* bo_l = bo + (size_t)l * DIM;
        const float* F1_l = F1 + (size_t)l * DIM * DFF;  const float* f1_l = f1 + (size_t)l * DFF;
        const float* F2_l = F2 + (size_t)l * DFF * DIM;  const float* f2_l = f2 + (size_t)l * DIM;
        const float* g1_l = g1 + (size_t)l * DIM;        const float* be1_l= be1+ (size_t)l * DIM;
        const float* g2_l = g2 + (size_t)l * DIM;        const float* be2_l= be2+ (size_t)l * DIM;

        // QKV projections
        gemm128<false,true,false><<<gemm_grid(TT, DIM, 1), 256>>>(
            x, Wq_l, bq_l, q, TT, DIM, DIM, DIM, DIM, DIM, 0, 0, 0);
        gemm128<false,true,false><<<gemm_grid(TT, DIM, 1), 256>>>(
            x, Wk_l, bk_l, k, TT, DIM, DIM, DIM, DIM, DIM, 0, 0, 0);
        gemm128<false,true,false><<<gemm_grid(TT, DIM, 1), 256>>>(
            x, Wv_l, bv_l, vv, TT, DIM, DIM, DIM, DIM, DIM, 0, 0, 0);

        // scores: S[h] = Q_h @ K_h^T (batched over heads via z, head offset = h*96)
        gemm128<true,false,false><<<gemm_grid(TT, TT, NHEAD), 256>>>(
            q, k, nullptr, S, TT, TT, DK, DIM, DIM, TT,
            (long)DK, (long)DK, (long)TT * TT);

        // softmax (scale fused)
        softmax_kernel<<<dim3(TT, NHEAD), 256>>>(S, scale);

        // attn_h = S[h] @ V_h
        gemm128<false,false,false><<<gemm_grid(TT, DK, NHEAD), 256>>>(
            S, vv, nullptr, attn, TT, DK, TT, TT, DIM, DIM,
            (long)TT * TT, (long)DK, (long)DK);

        // output projection + residual LN
        gemm128<false,true,false><<<gemm_grid(TT, DIM, 1), 256>>>(
            attn, Wo_l, bo_l, tmp, TT, DIM, DIM, DIM, DIM, DIM, 0, 0, 0);
        add_ln_kernel<<<TT, 256>>>(x, tmp, g1_l, be1_l);

        // FFN + residual LN
        gemm128<false,true,true><<<gemm_grid(TT, DFF, 1), 256>>>(
            x, F1_l, f1_l, ffn, TT, DFF, DIM, DIM, DFF, DFF, 0, 0, 0);
        gemm128<false,true,false><<<gemm_grid(TT, DIM, 1), 256>>>(
            ffn, F2_l, f2_l, tmp, TT, DIM, DFF, DFF, DIM, DIM, 0, 0, 0);
        add_ln_kernel<<<TT, 256>>>(x, tmp, g2_l, be2_l);
    }

    // 5) final gather + LN + predictor + bag max
    final_kernel<<<BAG, 256>>>(x, ng, nb, Wp, bp, ht);
    writeout_kernel<<<1, 128>>>(ht, out, out_size);
}

// round 5
// speedup vs baseline: 1.9494x; 1.9255x over previous
#include <cuda_runtime.h>
#include <cuda_bf16.h>
#include <cstdint>

// ---------------- problem constants ----------------
#define BAG  8
#define SEQ  512
#define DIM  768
#define NPD  6
#define NN_  48          // N nodes
#define TT   2304        // T = N*N
#define NHEAD 8
#define DK   96
#define DFF  1024
#define NLAYER 4
#define NREL 97

typedef uint32_t u32;

// ---------------- device scratch (no allocations allowed) ----------------
__device__ float g_htb [NN_ * DIM];
__device__ float g_u   [NN_ * DIM];
__device__ float g_v   [NN_ * DIM];
__device__ float g_x   [TT * DIM];
__device__ float g_q   [TT * DIM];
__device__ float g_k   [TT * DIM];
__device__ float g_vv  [TT * DIM];
__device__ float g_attn[TT * DIM];
__device__ float g_tmp [TT * DIM];
__device__ float g_ffn [TT * DFF];
__device__ float g_S   [(size_t)NHEAD * TT * TT];   // 170 MB attention scores
__device__ float g_ht  [BAG * NREL];

// ---------------- tf32 helpers ----------------
__device__ __forceinline__ u32 f2tf32(float f) {
    u32 r; asm("cvt.rna.tf32.f32 %0, %1;" : "=r"(r) : "f"(f)); return r;
}
__device__ __forceinline__ void mma_tf32(float& c0, float& c1, float& c2, float& c3,
                                         u32 a0, u32 a1, u32 a2, u32 a3,
                                         u32 b0, u32 b1) {
    asm("mma.sync.aligned.m16n8k8.row.col.f32.tf32.tf32.f32 "
        "{%0,%1,%2,%3}, {%4,%5,%6,%7}, {%8,%9}, {%0,%1,%2,%3};"
        : "+f"(c0), "+f"(c1), "+f"(c2), "+f"(c3)
        : "r"(a0), "r"(a1), "r"(a2), "r"(a3), "r"(b0), "r"(b1));
}

// ---------------- block reduction helper ----------------
__device__ __forceinline__ float blk_reduce(float val, float* sh, bool do_max) {
    const unsigned mask = 0xffffffffu;
#pragma unroll
    for (int o = 16; o > 0; o >>= 1) {
        float other = __shfl_xor_sync(mask, val, o);
        val = do_max ? fmaxf(val, other) : (val + other);
    }
    int lane = threadIdx.x & 31, w = threadIdx.x >> 5;
    __syncthreads();
    if (lane == 0) sh[w] = val;
    __syncthreads();
    int nw = (blockDim.x + 31) >> 5;
    if (w == 0) {
        val = (lane < nw) ? sh[lane] : (do_max ? -3.4e38f : 0.f);
#pragma unroll
        for (int o = 16; o > 0; o >>= 1) {
            float other = __shfl_xor_sync(mask, val, o);
            val = do_max ? fmaxf(val, other) : (val + other);
        }
        if (lane == 0) sh[0] = val;
    }
    __syncthreads();
    return sh[0];
}

// ---------------- 128x128 tf32 tensor-core GEMM ----------------
// C[m,n] = sum_k A[m,k] * (TRANSB ? B[n,k] : B[k,n])  (+bias) (ReLU)
// Requires K % 16 == 0, N % 4 == 0 (true for all call sites).
template<bool TRANSB, bool BIAS, bool RELU>
__global__ __launch_bounds__(256, 1)
void gemm_tc(const float* __restrict__ A, const float* __restrict__ B,
             const float* __restrict__ bias, float* __restrict__ C,
             int M, int N, int K, int lda, int ldb, int ldc,
             long sA, long sB, long sC)
{
    constexpr int BM = 128, BN = 128, BK = 16;
    constexpr int AP = BK + 4;                    // A pitch (20) -> conflict-free frags
    constexpr int BROWS = TRANSB ? BN : BK;
    constexpr int BP    = TRANSB ? (BK + 4) : (BN + 8);   // 20 or 136

    A += (long)blockIdx.z * sA;
    B += (long)blockIdx.z * sB;
    C += (long)blockIdx.z * sC;

    __shared__ u32 As[2][BM][AP];
    __shared__ u32 Bs[2][BROWS][BP];

    const int tid  = threadIdx.x;
    const int lane = tid & 31;
    const int warp = tid >> 5;
    const int wR   = (warp & 1) * 64;     // warp row base (2 warps in M)
    const int wC   = (warp >> 1) * 32;    // warp col base (4 warps in N)
    const int row0 = blockIdx.y * BM;
    const int col0 = blockIdx.x * BN;
    const int lr   = lane >> 2;           // 0..7
    const int lc   = lane & 3;            // 0..3

    // staging maps
    const int ar = tid >> 1;                  // A row 0..127
    const int ac = (tid & 1) * 8;             // A k offset 0 or 8
    const int bk = tid >> 4;                  // non-trans: B k row 0..15
    const int bn = (tid & 15) * 8;            // non-trans: B n offset
    // trans B uses ar/ac mapping on rows n

    const float4 f4z = make_float4(0.f, 0.f, 0.f, 0.f);
    float4 fa0, fa1, fb0, fb1;

    float acc[4][4][4];
#pragma unroll
    for (int i = 0; i < 4; i++)
#pragma unroll
        for (int j = 0; j < 4; j++)
#pragma unroll
            for (int c = 0; c < 4; c++) acc[i][j][c] = 0.f;

    const int KT = K / BK;

    auto fetch = [&](int k0) {
        int gm = row0 + ar;
        const float* ap = A + (long)gm * lda + k0 + ac;
        fa0 = (gm < M) ? *(const float4*)ap : f4z;
        fa1 = (gm < M) ? *(const float4*)(ap + 4) : f4z;
        if (TRANSB) {
            int gn = col0 + ar;
            const float* bp = B + (long)gn * ldb + k0 + ac;
            fb0 = (gn < N) ? *(const float4*)bp : f4z;
            fb1 = (gn < N) ? *(const float4*)(bp + 4) : f4z;
        } else {
            int gn = col0 + bn;
            const float* bp = B + (long)(k0 + bk) * ldb + gn;
            fb0 = (gn < N)     ? *(const float4*)bp : f4z;
            fb1 = (gn + 4 < N) ? *(const float4*)(bp + 4) : f4z;
        }
    };
    auto stage = [&](int buf) {
        u32* a = &As[buf][ar][ac];
        a[0] = f2tf32(fa0.x); a[1] = f2tf32(fa0.y); a[2] = f2tf32(fa0.z); a[3] = f2tf32(fa0.w);
        a[4] = f2tf32(fa1.x); a[5] = f2tf32(fa1.y); a[6] = f2tf32(fa1.z); a[7] = f2tf32(fa1.w);
        u32* b = TRANSB ? &Bs[buf][ar][ac] : &Bs[buf][bk][bn];
        b[0] = f2tf32(fb0.x); b[1] = f2tf32(fb0.y); b[2] = f2tf32(fb0.z); b[3] = f2tf32(fb0.w);
        b[4] = f2tf32(fb1.x); b[5] = f2tf32(fb1.y); b[6] = f2tf32(fb1.z); b[7] = f2tf32(fb1.w);
    };

    fetch(0);
    stage(0);
    __syncthreads();

    for (int kt = 0; kt < KT; kt++) {
        const int cur = kt & 1;
        const bool hn = (kt + 1 < KT);
        if (hn) fetch((kt + 1) * BK);

#pragma unroll
        for (int ks = 0; ks < 2; ks++) {
            const int k0 = ks * 8;
            u32 af[4][4], bf[4][2];
#pragma unroll
            for (int mt = 0; mt < 4; mt++) {
                int m = wR + mt * 16 + lr;
                af[mt][0] = As[cur][m][k0 + lc];
                af[mt][1] = As[cur][m + 8][k0 + lc];
                af[mt][2] = As[cur][m][k0 + lc + 4];
                af[mt][3] = As[cur][m + 8][k0 + lc + 4];
            }
#pragma unroll
            for (int nt = 0; nt < 4; nt++) {
                int n = wC + nt * 8 + lr;
                if (TRANSB) {
                    bf[nt][0] = Bs[cur][n][k0 + lc];
                    bf[nt][1] = Bs[cur][n][k0 + lc + 4];
                } else {
                    bf[nt][0] = Bs[cur][k0 + lc][n];
                    bf[nt][1] = Bs[cur][k0 + lc + 4][n];
                }
            }
#pragma unroll
            for (int mt = 0; mt < 4; mt++)
#pragma unroll
                for (int nt = 0; nt < 4; nt++)
                    mma_tf32(acc[mt][nt][0], acc[mt][nt][1], acc[mt][nt][2], acc[mt][nt][3],
                             af[mt][0], af[mt][1], af[mt][2], af[mt][3],
                             bf[nt][0], bf[nt][1]);
        }

        if (hn) stage(cur ^ 1);
        __syncthreads();
    }

    // ---- epilogue ----
#pragma unroll
    for (int nt = 0; nt < 4; nt++) {
        int gn = col0 + wC + nt * 8 + 2 * lc;
        float b0 = 0.f, b1 = 0.f;
        if (BIAS && gn < N)     b0 = bias[gn];
        if (BIAS && gn + 1 < N) b1 = bias[gn + 1];
#pragma unroll
        for (int mt = 0; mt < 4; mt++) {
            int gm0 = row0 + wR + mt * 16 + lr;
#pragma unroll
            for (int h = 0; h < 2; h++) {
                int gm = gm0 + h * 8;
                if (gm >= M) continue;
                float v0 = acc[mt][nt][2 * h]     + b0;
                float v1 = acc[mt][nt][2 * h + 1] + b1;
                if (RELU) { v0 = fmaxf(v0, 0.f); v1 = fmaxf(v1, 0.f); }
                if (gn + 1 < N) {
                    *(float2*)(C + (long)gm * ldc + gn) = make_float2(v0, v1);
                } else if (gn < N) {
                    C[(long)gm * ldc + gn] = v0;
                }
            }
        }
    }
}

// ---------------- span max pooling ----------------
__global__ void pool_kernel(const float* __restrict__ emb, const int* __restrict__ spans,
                            float* __restrict__ htb)
{
    int node = blockIdx.x;                 // 0..47
    int bag  = node / NPD;
    int s0 = spans[node * 2 + 0];
    int s1 = spans[node * 2 + 1];
    const float* base = emb + (long)bag * SEQ * DIM;
    for (int d = threadIdx.x; d < DIM; d += blockDim.x) {
        float m = -3.4e38f;
        for (int p = s0; p <= s1; p++)
            m = fmaxf(m, base[(long)p * DIM + d]);
        htb[(long)node * DIM + d] = m;
    }
}

// ---------------- pairwise relu(u_i + v_j) ----------------
__global__ void build_pair_kernel(const float* __restrict__ u, const float* __restrict__ v,
                                  float* __restrict__ out)
{
    int t = blockIdx.x;         // 0..2303
    int i = t / NN_, j = t % NN_;
    const float* ur = u + (long)i * DIM;
    const float* vr = v + (long)j * DIM;
    float* o = out + (long)t * DIM;
#pragma unroll
    for (int it = 0; it < DIM / 256; it++) {
        int d = threadIdx.x + it * 256;
        o[d] = fmaxf(ur[d] + vr[d], 0.f);
    }
}

// ---------------- softmax over score rows (scale fused) ----------------
__global__ void softmax_kernel(float* __restrict__ S, float scale)
{
    long base = ((long)blockIdx.y * TT + blockIdx.x) * TT;
    float* row = S + base;
    __shared__ float sh[32];
    float v[9];
    float m = -3.4e38f;
#pragma unroll
    for (int i = 0; i < 9; i++) {
        v[i] = row[threadIdx.x + i * 256] * scale;
        m = fmaxf(m, v[i]);
    }
    m = blk_reduce(m, sh, true);
    float s = 0.f;
#pragma unroll
    for (int i = 0; i < 9; i++) {
        v[i] = __expf(v[i] - m);
        s += v[i];
    }
    s = blk_reduce(s, sh, false);
    float inv = 1.f / s;
#pragma unroll
    for (int i = 0; i < 9; i++)
        row[threadIdx.x + i * 256] = v[i] * inv;
}

// ---------------- x = LN(x + o) * g + b ----------------
__global__ void add_ln_kernel(float* __restrict__ x, const float* __restrict__ o,
                              const float* __restrict__ g, const float* __restrict__ b)
{
    long base = (long)blockIdx.x * DIM;
    float* xr = x + base;
    const float* orr = o + base;
    __shared__ float sh[32];
    float v[3];
    float s = 0.f, s2 = 0.f;
#pragma unroll
    for (int i = 0; i < 3; i++) {
        int d = threadIdx.x + i * 256;
        float t = xr[d] + orr[d];
        v[i] = t; s += t; s2 += t * t;
    }
    s  = blk_reduce(s,  sh, false);
    s2 = blk_reduce(s2, sh, false);
    float mean = s * (1.f / DIM);
    float var  = s2 * (1.f / DIM) - mean * mean;
    float inv  = rsqrtf(var + 1e-5f);
#pragma unroll
    for (int i = 0; i < 3; i++) {
        int d = threadIdx.x + i * 256;
        xr[d] = (v[i] - mean) * inv * g[d] + b[d];
    }
}

// ---------------- final: gather (h,t) cells, LN, predictor ----------------
__global__ void final_kernel(const float* __restrict__ x, const float* __restrict__ ng,
                             const float* __restrict__ nb, const float* __restrict__ Wp,
                             const float* __restrict__ bp, float* __restrict__ ht)
{
    int bag = blockIdx.x;
    long r = (long)(bag * NPD) * NN_ + (bag * NPD + 1);
    const float* row = x + r * DIM;
    __shared__ float sh[DIM];
    __shared__ float red[32];
    float s = 0.f, s2 = 0.f;
    for (int d = threadIdx.x; d < DIM; d += blockDim.x) {
        float t = row[d];
        sh[d] = t; s += t; s2 += t * t;
    }
    s  = blk_reduce(s,  red, false);
    s2 = blk_reduce(s2, red, false);
    float mean = s * (1.f / DIM);
    float inv  = rsqrtf(s2 * (1.f / DIM) - mean * mean + 1e-5f);
    __syncthreads();
    for (int d = threadIdx.x; d < DIM; d += blockDim.x)
        sh[d] = (sh[d] - mean) * inv * ng[d] + nb[d];
    __syncthreads();
    for (int n = threadIdx.x; n < NREL; n += blockDim.x) {
        float acc = bp[n];
        for (int k = 0; k < DIM; k++)
            acc = fmaf(sh[k], Wp[(long)k * NREL + n], acc);
        ht[bag * NREL + n] = acc;
    }
}

// ---------------- output assembly: bag max + layout ----------------
__global__ void writeout_kernel(const float* __restrict__ ht, float* __restrict__ out,
                                int out_size)
{
    int n = threadIdx.x;
    if (n >= NREL) return;
    float m = -3.4e38f;
    for (int b = 0; b < BAG; b++) m = fmaxf(m, ht[b * NREL + n]);
    if (out_size >= NREL * (BAG + 1)) {
        out[n] = m;
        for (int b = 0; b < BAG; b++) out[NREL + b * NREL + n] = ht[b * NREL + n];
    } else if (out_size == NREL) {
        out[n] = m;
    } else {
        for (int b = 0; b < BAG; b++) out[b * NREL + n] = ht[b * NREL + n];
    }
}

// ---------------- host ----------------
static inline dim3 gemm_grid(int M, int N, int Z) {
    return dim3((unsigned)((N + 127) / 128), (unsigned)((M + 127) / 128), (unsigned)Z);
}

template <typename T>
static inline float* sym(T& s) {
    void* p = nullptr;
    cudaGetSymbolAddress(&p, s);
    return (float*)p;
}

extern "C" void kernel_launch(void* const* d_in, const int* in_sizes, int n_in,
                              void* d_out, int out_size)
{
    const float* emb   = (const float*)d_in[0];
    const int*   spans = (const int*)  d_in[1];
    const float* Wu = (const float*)d_in[2];  const float* bu = (const float*)d_in[3];
    const float* Wv = (const float*)d_in[4];  const float* bv = (const float*)d_in[5];
    const float* Wl = (const float*)d_in[6];  const float* bl = (const float*)d_in[7];
    const float* Wq = (const float*)d_in[8];  const float* bq = (const float*)d_in[9];
    const float* Wk = (const float*)d_in[10]; const float* bk = (const float*)d_in[11];
    const float* Wvm= (const float*)d_in[12]; const float* bvm= (const float*)d_in[13];
    const float* Wo = (const float*)d_in[14]; const float* bo = (const float*)d_in[15];
    const float* F1 = (const float*)d_in[16]; const float* f1 = (const float*)d_in[17];
    const float* F2 = (const float*)d_in[18]; const float* f2 = (const float*)d_in[19];
    const float* g1 = (const float*)d_in[20]; const float* be1= (const float*)d_in[21];
    const float* g2 = (const float*)d_in[22]; const float* be2= (const float*)d_in[23];
    const float* ng = (const float*)d_in[24]; const float* nb = (const float*)d_in[25];
    const float* Wp = (const float*)d_in[26]; const float* bp = (const float*)d_in[27];

    float* htb = sym(g_htb);
    float* u   = sym(g_u);
    float* v   = sym(g_v);
    float* x   = sym(g_x);
    float* q   = sym(g_q);
    float* k   = sym(g_k);
    float* vv  = sym(g_vv);
    float* attn= sym(g_attn);
    float* tmp = sym(g_tmp);
    float* ffn = sym(g_ffn);
    float* S   = sym(g_S);
    float* ht  = sym(g_ht);
    float* out = (float*)d_out;

    const float scale = 0.102062072615966f;   // 1/sqrt(96)

    // 1) span max pooling -> htb [48,768]
    pool_kernel<<<NN_, 256>>>(emb, spans, htb);

    // 2) u = htb@Wu+bu ; v = htb@Wv+bv
    gemm_tc<false,true,false><<<gemm_grid(NN_, DIM, 1), 256>>>(
        htb, Wu, bu, u, NN_, DIM, DIM, DIM, DIM, DIM, 0, 0, 0);
    gemm_tc<false,true,false><<<gemm_grid(NN_, DIM, 1), 256>>>(
        htb, Wv, bv, v, NN_, DIM, DIM, DIM, DIM, DIM, 0, 0, 0);

    // 3) pair = relu(u_i + v_j) ; x = relu(pair @ Wl + bl)
    build_pair_kernel<<<TT, 256>>>(u, v, tmp);
    gemm_tc<false,true,true><<<gemm_grid(TT, DIM, 1), 256>>>(
        tmp, Wl, bl, x, TT, DIM, DIM, DIM, DIM, DIM, 0, 0, 0);

    // 4) MatTransformer layers
    for (int l = 0; l < NLAYER; l++) {
        const float* Wq_l = Wq + (size_t)l * DIM * DIM;  const float* bq_l = bq + (size_t)l * DIM;
        const float* Wk_l = Wk + (size_t)l * DIM * DIM;  const float* bk_l = bk + (size_t)l * DIM;
        const float* Wv_l = Wvm+ (size_t)l * DIM * DIM;  const float* bv_l = bvm+ (size_t)l * DIM;
        const float* Wo_l = Wo + (size_t)l * DIM * DIM;  const float* bo_l = bo + (size_t)l * DIM;
        const float* F1_l = F1 + (size_t)l * DIM * DFF;  const float* f1_l = f1 + (size_t)l * DFF;
        const float* F2_l = F2 + (size_t)l * DFF * DIM;  const float* f2_l = f2 + (size_t)l * DIM;
        const float* g1_l = g1 + (size_t)l * DIM;        const float* be1_l= be1+ (size_t)l * DIM;
        const float* g2_l = g2 + (size_t)l * DIM;        const float* be2_l= be2+ (size_t)l * DIM;

        // QKV projections
        gemm_tc<false,true,false><<<gemm_grid(TT, DIM, 1), 256>>>(
            x, Wq_l, bq_l, q, TT, DIM, DIM, DIM, DIM, DIM, 0, 0, 0);
        gemm_tc<false,true,false><<<gemm_grid(TT, DIM, 1), 256>>>(
            x, Wk_l, bk_l, k, TT, DIM, DIM, DIM, DIM, DIM, 0, 0, 0);
        gemm_tc<false,true,false><<<gemm_grid(TT, DIM, 1), 256>>>(
            x, Wv_l, bv_l, vv, TT, DIM, DIM, DIM, DIM, DIM, 0, 0, 0);

        // scores: S[h] = Q_h @ K_h^T (batched over heads via z, head offset = h*96)
        gemm_tc<true,false,false><<<gemm_grid(TT, TT, NHEAD), 256>>>(
            q, k, nullptr, S, TT, TT, DK, DIM, DIM, TT,
            (long)DK, (long)DK, (long)TT * TT);

        // softmax (scale fused)
        softmax_kernel<<<dim3(TT, NHEAD), 256>>>(S, scale);

        // attn_h = S[h] @ V_h
        gemm_tc<false,false,false><<<gemm_grid(TT, DK, NHEAD), 256>>>(
            S, vv, nullptr, attn, TT, DK, TT, TT, DIM, DIM,
            (long)TT * TT, (long)DK, (long)DK);

        // output projection + residual LN
        gemm_tc<false,true,false><<<gemm_grid(TT, DIM, 1), 256>>>(
            attn, Wo_l, bo_l, tmp, TT, DIM, DIM, DIM, DIM, DIM, 0, 0, 0);
        add_ln_kernel<<<TT, 256>>>(x, tmp, g1_l, be1_l);

        // FFN + residual LN
        gemm_tc<false,true,true><<<gemm_grid(TT, DFF, 1), 256>>>(
            x, F1_l, f1_l, ffn, TT, DFF, DIM, DIM, DFF, DFF, 0, 0, 0);
        gemm_tc<false,true,false><<<gemm_grid(TT, DIM, 1), 256>>>(
            ffn, F2_l, f2_l, tmp, TT, DIM, DFF, DFF, DIM, DIM, 0, 0, 0);
        add_ln_kernel<<<TT, 256>>>(x, tmp, g2_l, be2_l);
    }

    // 5) final gather + LN + predictor + bag max
    final_kernel<<<BAG, 256>>>(x, ng, nb, Wp, bp, ht);
    writeout_kernel<<<1, 128>>>(ht, out, out_size);
}

// round 6
// speedup vs baseline: 2.7719x; 1.4219x over previous
#include <cuda_runtime.h>
#include <cuda_bf16.h>
#include <cstdint>

// ---------------- problem constants ----------------
#define BAG  8
#define SEQ  512
#define DIM  768
#define NPD  6
#define NN_  48          // N nodes
#define TT   2304        // T = N*N
#define NHEAD 8
#define DK   96
#define DFF  1024
#define NLAYER 4
#define NREL 97

typedef uint32_t u32;

// ---------------- device scratch (no allocations allowed) ----------------
__device__ float g_htb [NN_ * DIM];
__device__ float g_u   [NN_ * DIM];
__device__ float g_v   [NN_ * DIM];
__device__ float g_x   [TT * DIM];
__device__ float g_q   [TT * DIM];
__device__ float g_k   [TT * DIM];
__device__ float g_vv  [TT * DIM];
__device__ float g_attn[TT * DIM];
__device__ float g_tmp [TT * DIM];
__device__ float g_ffn [TT * DFF];
__device__ float g_ht  [BAG * NREL];

// ---------------- tf32 helpers ----------------
__device__ __forceinline__ u32 f2tf32(float f) {
    u32 r; asm("cvt.rna.tf32.f32 %0, %1;" : "=r"(r) : "f"(f)); return r;
}
__device__ __forceinline__ void mma_tf32(float& c0, float& c1, float& c2, float& c3,
                                         u32 a0, u32 a1, u32 a2, u32 a3,
                                         u32 b0, u32 b1) {
    asm("mma.sync.aligned.m16n8k8.row.col.f32.tf32.tf32.f32 "
        "{%0,%1,%2,%3}, {%4,%5,%6,%7}, {%8,%9}, {%0,%1,%2,%3};"
        : "+f"(c0), "+f"(c1), "+f"(c2), "+f"(c3)
        : "r"(a0), "r"(a1), "r"(a2), "r"(a3), "r"(b0), "r"(b1));
}

// ---------------- block reduction helper ----------------
__device__ __forceinline__ float blk_reduce(float val, float* sh, bool do_max) {
    const unsigned mask = 0xffffffffu;
#pragma unroll
    for (int o = 16; o > 0; o >>= 1) {
        float other = __shfl_xor_sync(mask, val, o);
        val = do_max ? fmaxf(val, other) : (val + other);
    }
    int lane = threadIdx.x & 31, w = threadIdx.x >> 5;
    __syncthreads();
    if (lane == 0) sh[w] = val;
    __syncthreads();
    int nw = (blockDim.x + 31) >> 5;
    if (w == 0) {
        val = (lane < nw) ? sh[lane] : (do_max ? -3.4e38f : 0.f);
#pragma unroll
        for (int o = 16; o > 0; o >>= 1) {
            float other = __shfl_xor_sync(mask, val, o);
            val = do_max ? fmaxf(val, other) : (val + other);
        }
        if (lane == 0) sh[0] = val;
    }
    __syncthreads();
    return sh[0];
}

// ---------------- 128x128 tf32 tensor-core GEMM ----------------
template<bool TRANSB, bool BIAS, bool RELU>
__global__ __launch_bounds__(256, 1)
void gemm_tc(const float* __restrict__ A, const float* __restrict__ B,
             const float* __restrict__ bias, float* __restrict__ C,
             int M, int N, int K, int lda, int ldb, int ldc,
             long sA, long sB, long sC)
{
    constexpr int BM = 128, BN = 128, BK = 16;
    constexpr int AP = BK + 4;
    constexpr int BROWS = TRANSB ? BN : BK;
    constexpr int BP    = TRANSB ? (BK + 4) : (BN + 8);

    A += (long)blockIdx.z * sA;
    B += (long)blockIdx.z * sB;
    C += (long)blockIdx.z * sC;

    __shared__ u32 As[2][BM][AP];
    __shared__ u32 Bs[2][BROWS][BP];

    const int tid  = threadIdx.x;
    const int lane = tid & 31;
    const int warp = tid >> 5;
    const int wR   = (warp & 1) * 64;
    const int wC   = (warp >> 1) * 32;
    const int row0 = blockIdx.y * BM;
    const int col0 = blockIdx.x * BN;
    const int lr   = lane >> 2;
    const int lc   = lane & 3;

    const int ar = tid >> 1;
    const int ac = (tid & 1) * 8;
    const int bkr = tid >> 4;
    const int bn = (tid & 15) * 8;

    const float4 f4z = make_float4(0.f, 0.f, 0.f, 0.f);
    float4 fa0, fa1, fb0, fb1;

    float acc[4][4][4];
#pragma unroll
    for (int i = 0; i < 4; i++)
#pragma unroll
        for (int j = 0; j < 4; j++)
#pragma unroll
            for (int c = 0; c < 4; c++) acc[i][j][c] = 0.f;

    const int KT = K / BK;

    auto fetch = [&](int k0) {
        int gm = row0 + ar;
        const float* ap = A + (long)gm * lda + k0 + ac;
        fa0 = (gm < M) ? *(const float4*)ap : f4z;
        fa1 = (gm < M) ? *(const float4*)(ap + 4) : f4z;
        if (TRANSB) {
            int gn = col0 + ar;
            const float* bp = B + (long)gn * ldb + k0 + ac;
            fb0 = (gn < N) ? *(const float4*)bp : f4z;
            fb1 = (gn < N) ? *(const float4*)(bp + 4) : f4z;
        } else {
            int gn = col0 + bn;
            const float* bp = B + (long)(k0 + bkr) * ldb + gn;
            fb0 = (gn < N)     ? *(const float4*)bp : f4z;
            fb1 = (gn + 4 < N) ? *(const float4*)(bp + 4) : f4z;
        }
    };
    auto stage = [&](int buf) {
        u32* a = &As[buf][ar][ac];
        a[0] = f2tf32(fa0.x); a[1] = f2tf32(fa0.y); a[2] = f2tf32(fa0.z); a[3] = f2tf32(fa0.w);
        a[4] = f2tf32(fa1.x); a[5] = f2tf32(fa1.y); a[6] = f2tf32(fa1.z); a[7] = f2tf32(fa1.w);
        u32* b = TRANSB ? &Bs[buf][ar][ac] : &Bs[buf][bkr][bn];
        b[0] = f2tf32(fb0.x); b[1] = f2tf32(fb0.y); b[2] = f2tf32(fb0.z); b[3] = f2tf32(fb0.w);
        b[4] = f2tf32(fb1.x); b[5] = f2tf32(fb1.y); b[6] = f2tf32(fb1.z); b[7] = f2tf32(fb1.w);
    };

    fetch(0);
    stage(0);
    __syncthreads();

    for (int kt = 0; kt < KT; kt++) {
        const int cur = kt & 1;
        const bool hn = (kt + 1 < KT);
        if (hn) fetch((kt + 1) * BK);

#pragma unroll
        for (int ks = 0; ks < 2; ks++) {
            const int k0 = ks * 8;
            u32 af[4][4], bf[4][2];
#pragma unroll
            for (int mt = 0; mt < 4; mt++) {
                int m = wR + mt * 16 + lr;
                af[mt][0] = As[cur][m][k0 + lc];
                af[mt][1] = As[cur][m + 8][k0 + lc];
                af[mt][2] = As[cur][m][k0 + lc + 4];
                af[mt][3] = As[cur][m + 8][k0 + lc + 4];
            }
#pragma unroll
            for (int nt = 0; nt < 4; nt++) {
                int n = wC + nt * 8 + lr;
                if (TRANSB) {
                    bf[nt][0] = Bs[cur][n][k0 + lc];
                    bf[nt][1] = Bs[cur][n][k0 + lc + 4];
                } else {
                    bf[nt][0] = Bs[cur][k0 + lc][n];
                    bf[nt][1] = Bs[cur][k0 + lc + 4][n];
                }
            }
#pragma unroll
            for (int mt = 0; mt < 4; mt++)
#pragma unroll
                for (int nt = 0; nt < 4; nt++)
                    mma_tf32(acc[mt][nt][0], acc[mt][nt][1], acc[mt][nt][2], acc[mt][nt][3],
                             af[mt][0], af[mt][1], af[mt][2], af[mt][3],
                             bf[nt][0], bf[nt][1]);
        }

        if (hn) stage(cur ^ 1);
        __syncthreads();
    }

#pragma unroll
    for (int nt = 0; nt < 4; nt++) {
        int gn = col0 + wC + nt * 8 + 2 * lc;
        float b0 = 0.f, b1 = 0.f;
        if (BIAS && gn < N)     b0 = bias[gn];
        if (BIAS && gn + 1 < N) b1 = bias[gn + 1];
#pragma unroll
        for (int mt = 0; mt < 4; mt++) {
            int gm0 = row0 + wR + mt * 16 + lr;
#pragma unroll
            for (int h = 0; h < 2; h++) {
                int gm = gm0 + h * 8;
                if (gm >= M) continue;
                float v0 = acc[mt][nt][2 * h]     + b0;
                float v1 = acc[mt][nt][2 * h + 1] + b1;
                if (RELU) { v0 = fmaxf(v0, 0.f); v1 = fmaxf(v1, 0.f); }
                if (gn + 1 < N) {
                    *(float2*)(C + (long)gm * ldc + gn) = make_float2(v0, v1);
                } else if (gn < N) {
                    C[(long)gm * ldc + gn] = v0;
                }
            }
        }
    }
}

// ---------------- flash attention (tf32 MMA, online softmax) ----------------
// Grid: (TT/128, NHEAD). 256 threads (8 warps; warp = 16 Q rows).
// Smem word layout (u32):
//   Qs [128][100]            @ 0
//   Ks [2][64][100]          @ 12800
//   Vs [2][64][104]          @ 25600
//   Ps [128][68]             @ 38912
#define FQ_P 100
#define FK_P 100
#define FV_P 104
#define FP_P 68
#define FQ_OFF 0
#define FK_OFF 12800
#define FV_OFF 25600
#define FP_OFF 38912
#define FLASH_SMEM ((38912 + 128 * 68) * 4)

__global__ __launch_bounds__(256, 1)
void flash_kernel(const float* __restrict__ Q, const float* __restrict__ K,
                  const float* __restrict__ V, float* __restrict__ O, float scale)
{
    extern __shared__ u32 sm[];
    u32* Qs = sm + FQ_OFF;
    u32* Ks = sm + FK_OFF;   // [2][64][FK_P]
    u32* Vs = sm + FV_OFF;   // [2][64][FV_P]
    u32* Ps = sm + FP_OFF;   // [128][FP_P]

    const int tid  = threadIdx.x;
    const int lane = tid & 31;
    const int warp = tid >> 5;
    const int lr   = lane >> 2;     // 0..7
    const int lc   = lane & 3;      // 0..3
    const int wm   = warp * 16;     // warp's Q-row base in tile
    const int mt0  = blockIdx.x * 128;   // global Q-row base
    const int head = blockIdx.y;

    const float* Qb = Q + (long)mt0 * DIM + head * DK;
    const float* Kb = K + head * DK;
    const float* Vb = V + head * DK;

    // ---- load Q tile (128 x 96) as tf32 ----
    {
        const int row = tid >> 1;            // pairs: 2 threads per row? No: 12 f4/thread map
    }
#pragma unroll
    for (int it = 0; it < 12; it++) {
        int id  = tid + it * 256;            // 0..3071
        int row = id / 24;
        int c4  = (id % 24) * 4;
        float4 f = *(const float4*)(Qb + (long)row * DIM + c4);
        u32* d = Qs + row * FQ_P + c4;
        d[0] = f2tf32(f.x); d[1] = f2tf32(f.y); d[2] = f2tf32(f.z); d[3] = f2tf32(f.w);
    }

    // ---- K/V prefetch machinery (64 x 96 tiles) ----
    float4 rk[6], rv[6];
    auto fetch = [&](int t) {
        int kv0 = t * 64;
#pragma unroll
        for (int it = 0; it < 6; it++) {
            int id  = tid + it * 256;        // 0..1535
            int row = id / 24;
            int c4  = (id % 24) * 4;
            rk[it] = *(const float4*)(Kb + (long)(kv0 + row) * DIM + c4);
            rv[it] = *(const float4*)(Vb + (long)(kv0 + row) * DIM + c4);
        }
    };
    auto stage = [&](int buf) {
#pragma unroll
        for (int it = 0; it < 6; it++) {
            int id  = tid + it * 256;
            int row = id / 24;
            int c4  = (id % 24) * 4;
            u32* dk = Ks + (buf * 64 + row) * FK_P + c4;
            dk[0] = f2tf32(rk[it].x); dk[1] = f2tf32(rk[it].y);
            dk[2] = f2tf32(rk[it].z); dk[3] = f2tf32(rk[it].w);
            u32* dv = Vs + (buf * 64 + row) * FV_P + c4;
            dv[0] = f2tf32(rv[it].x); dv[1] = f2tf32(rv[it].y);
            dv[2] = f2tf32(rv[it].z); dv[3] = f2tf32(rv[it].w);
        }
    };

    float oacc[12][4];
#pragma unroll
    for (int i = 0; i < 12; i++)
#pragma unroll
        for (int c = 0; c < 4; c++) oacc[i][c] = 0.f;
    float mrow0 = -1e30f, mrow1 = -1e30f, lrow0 = 0.f, lrow1 = 0.f;

    fetch(0);
    stage(0);
    __syncthreads();

    const int NIT = TT / 64;   // 36
    for (int t = 0; t < NIT; t++) {
        const int cur = t & 1;
        const bool hn = (t + 1 < NIT);
        if (hn) fetch(t + 1);

        // ---- S = Q K^T over this 64-kv tile (warp: 16 x 64) ----
        float sacc[8][4];
#pragma unroll
        for (int nt = 0; nt < 8; nt++)
#pragma unroll
            for (int c = 0; c < 4; c++) sacc[nt][c] = 0.f;

#pragma unroll
        for (int ks = 0; ks < 12; ks++) {
            const int k0 = ks * 8;
            u32 a0 = Qs[(wm + lr) * FQ_P + k0 + lc];
            u32 a1 = Qs[(wm + lr + 8) * FQ_P + k0 + lc];
            u32 a2 = Qs[(wm + lr) * FQ_P + k0 + lc + 4];
            u32 a3 = Qs[(wm + lr + 8) * FQ_P + k0 + lc + 4];
#pragma unroll
            for (int nt = 0; nt < 8; nt++) {
                u32 b0 = Ks[(cur * 64 + nt * 8 + lr) * FK_P + k0 + lc];
                u32 b1 = Ks[(cur * 64 + nt * 8 + lr) * FK_P + k0 + lc + 4];
                mma_tf32(sacc[nt][0], sacc[nt][1], sacc[nt][2], sacc[nt][3],
                         a0, a1, a2, a3, b0, b1);
            }
        }

        // ---- online softmax (rows lr, lr+8; intra-warp over lc group) ----
        float rm0 = -1e30f, rm1 = -1e30f;
#pragma unroll
        for (int nt = 0; nt < 8; nt++) {
            rm0 = fmaxf(rm0, fmaxf(sacc[nt][0], sacc[nt][1]));
            rm1 = fmaxf(rm1, fmaxf(sacc[nt][2], sacc[nt][3]));
        }
        rm0 *= scale; rm1 *= scale;
#pragma unroll
        for (int o = 1; o <= 2; o <<= 1) {
            rm0 = fmaxf(rm0, __shfl_xor_sync(0xffffffffu, rm0, o));
            rm1 = fmaxf(rm1, __shfl_xor_sync(0xffffffffu, rm1, o));
        }
        float mn0 = fmaxf(mrow0, rm0);
        float mn1 = fmaxf(mrow1, rm1);
        float al0 = __expf(mrow0 - mn0);
        float al1 = __expf(mrow1 - mn1);
        float sum0 = 0.f, sum1 = 0.f;
#pragma unroll
        for (int nt = 0; nt < 8; nt++) {
            float p0 = __expf(sacc[nt][0] * scale - mn0);
            float p1 = __expf(sacc[nt][1] * scale - mn0);
            float p2 = __expf(sacc[nt][2] * scale - mn1);
            float p3 = __expf(sacc[nt][3] * scale - mn1);
            sum0 += p0 + p1; sum1 += p2 + p3;
            uint2 w0; w0.x = f2tf32(p0); w0.y = f2tf32(p1);
            uint2 w1; w1.x = f2tf32(p2); w1.y = f2tf32(p3);
            *(uint2*)&Ps[(wm + lr) * FP_P + nt * 8 + 2 * lc]     = w0;
            *(uint2*)&Ps[(wm + lr + 8) * FP_P + nt * 8 + 2 * lc] = w1;
        }
#pragma unroll
        for (int o = 1; o <= 2; o <<= 1) {
            sum0 += __shfl_xor_sync(0xffffffffu, sum0, o);
            sum1 += __shfl_xor_sync(0xffffffffu, sum1, o);
        }
        lrow0 = lrow0 * al0 + sum0;
        lrow1 = lrow1 * al1 + sum1;
        mrow0 = mn0; mrow1 = mn1;
#pragma unroll
        for (int nt = 0; nt < 12; nt++) {
            oacc[nt][0] *= al0; oacc[nt][1] *= al0;
            oacc[nt][2] *= al1; oacc[nt][3] *= al1;
        }
        __syncthreads();          // Ps visible; Ks[cur] fully consumed

        if (hn) stage(cur ^ 1);

        // ---- O += P V  (warp: 16 x 96) ----
#pragma unroll
        for (int ksv = 0; ksv < 8; ksv++) {
            const int k0 = ksv * 8;
            u32 a0 = Ps[(wm + lr) * FP_P + k0 + lc];
            u32 a1 = Ps[(wm + lr + 8) * FP_P + k0 + lc];
            u32 a2 = Ps[(wm + lr) * FP_P + k0 + lc + 4];
            u32 a3 = Ps[(wm + lr + 8) * FP_P + k0 + lc + 4];
#pragma unroll
            for (int nt = 0; nt < 12; nt++) {
                u32 b0 = Vs[(cur * 64 + k0 + lc) * FV_P + nt * 8 + lr];
                u32 b1 = Vs[(cur * 64 + k0 + lc + 4) * FV_P + nt * 8 + lr];
                mma_tf32(oacc[nt][0], oacc[nt][1], oacc[nt][2], oacc[nt][3],
                         a0, a1, a2, a3, b0, b1);
            }
        }
        __syncthreads();          // Vs[cur]/Ps consumed; stage STS complete
    }

    // ---- normalize + write ----
    float inv0 = 1.f / lrow0;
    float inv1 = 1.f / lrow1;
    int r0 = mt0 + wm + lr;
    int r1 = r0 + 8;
#pragma unroll
    for (int nt = 0; nt < 12; nt++) {
        int col = head * DK + nt * 8 + 2 * lc;
        *(float2*)(O + (long)r0 * DIM + col) = make_float2(oacc[nt][0] * inv0, oacc[nt][1] * inv0);
        *(float2*)(O + (long)r1 * DIM + col) = make_float2(oacc[nt][2] * inv1, oacc[nt][3] * inv1);
    }
}

// ---------------- span max pooling ----------------
__global__ void pool_kernel(const float* __restrict__ emb, const int* __restrict__ spans,
                            float* __restrict__ htb)
{
    int node = blockIdx.x;
    int bag  = node / NPD;
    int s0 = spans[node * 2 + 0];
    int s1 = spans[node * 2 + 1];
    const float* base = emb + (long)bag * SEQ * DIM;
    for (int d = threadIdx.x; d < DIM; d += blockDim.x) {
        float m = -3.4e38f;
        for (int p = s0; p <= s1; p++)
            m = fmaxf(m, base[(long)p * DIM + d]);
        htb[(long)node * DIM + d] = m;
    }
}

// ---------------- pairwise relu(u_i + v_j) ----------------
__global__ void build_pair_kernel(const float* __restrict__ u, const float* __restrict__ v,
                                  float* __restrict__ out)
{
    int t = blockIdx.x;
    int i = t / NN_, j = t % NN_;
    const float* ur = u + (long)i * DIM;
    const float* vr = v + (long)j * DIM;
    float* o = out + (long)t * DIM;
#pragma unroll
    for (int it = 0; it < DIM / 256; it++) {
        int d = threadIdx.x + it * 256;
        o[d] = fmaxf(ur[d] + vr[d], 0.f);
    }
}

// ---------------- x = LN(x + o) * g + b ----------------
__global__ void add_ln_kernel(float* __restrict__ x, const float* __restrict__ o,
                              const float* __restrict__ g, const float* __restrict__ b)
{
    long base = (long)blockIdx.x * DIM;
    float* xr = x + base;
    const float* orr = o + base;
    __shared__ float sh[32];
    float v[3];
    float s = 0.f, s2 = 0.f;
#pragma unroll
    for (int i = 0; i < 3; i++) {
        int d = threadIdx.x + i * 256;
        float t = xr[d] + orr[d];
        v[i] = t; s += t; s2 += t * t;
    }
    s  = blk_reduce(s,  sh, false);
    s2 = blk_reduce(s2, sh, false);
    float mean = s * (1.f / DIM);
    float var  = s2 * (1.f / DIM) - mean * mean;
    float inv  = rsqrtf(var + 1e-5f);
#pragma unroll
    for (int i = 0; i < 3; i++) {
        int d = threadIdx.x + i * 256;
        xr[d] = (v[i] - mean) * inv * g[d] + b[d];
    }
}

// ---------------- final: gather (h,t) cells, LN, predictor ----------------
__global__ void final_kernel(const float* __restrict__ x, const float* __restrict__ ng,
                             const float* __restrict__ nb, const float* __restrict__ Wp,
                             const float* __restrict__ bp, float* __restrict__ ht)
{
    int bag = blockIdx.x;
    long r = (long)(bag * NPD) * NN_ + (bag * NPD + 1);
    const float* row = x + r * DIM;
    __shared__ float sh[DIM];
    __shared__ float red[32];
    float s = 0.f, s2 = 0.f;
    for (int d = threadIdx.x; d < DIM; d += blockDim.x) {
        float t = row[d];
        sh[d] = t; s += t; s2 += t * t;
    }
    s  = blk_reduce(s,  red, false);
    s2 = blk_reduce(s2, red, false);
    float mean = s * (1.f / DIM);
    float inv  = rsqrtf(s2 * (1.f / DIM) - mean * mean + 1e-5f);
    __syncthreads();
    for (int d = threadIdx.x; d < DIM; d += blockDim.x)
        sh[d] = (sh[d] - mean) * inv * ng[d] + nb[d];
    __syncthreads();
    for (int n = threadIdx.x; n < NREL; n += blockDim.x) {
        float acc = bp[n];
        for (int k = 0; k < DIM; k++)
            acc = fmaf(sh[k], Wp[(long)k * NREL + n], acc);
        ht[bag * NREL + n] = acc;
    }
}

// ---------------- output assembly: bag max + layout ----------------
__global__ void writeout_kernel(const float* __restrict__ ht, float* __restrict__ out,
                                int out_size)
{
    int n = threadIdx.x;
    if (n >= NREL) return;
    float m = -3.4e38f;
    for (int b = 0; b < BAG; b++) m = fmaxf(m, ht[b * NREL + n]);
    if (out_size >= NREL * (BAG + 1)) {
        out[n] = m;
        for (int b = 0; b < BAG; b++) out[NREL + b * NREL + n] = ht[b * NREL + n];
    } else if (out_size == NREL) {
        out[n] = m;
    } else {
        for (int b = 0; b < BAG; b++) out[b * NREL + n] = ht[b * NREL + n];
    }
}

// ---------------- host ----------------
static inline dim3 gemm_grid(int M, int N, int Z) {
    return dim3((unsigned)((N + 127) / 128), (unsigned)((M + 127) / 128), (unsigned)Z);
}

template <typename T>
static inline float* sym(T& s) {
    void* p = nullptr;
    cudaGetSymbolAddress(&p, s);
    return (float*)p;
}

extern "C" void kernel_launch(void* const* d_in, const int* in_sizes, int n_in,
                              void* d_out, int out_size)
{
    const float* emb   = (const float*)d_in[0];
    const int*   spans = (const int*)  d_in[1];
    const float* Wu = (const float*)d_in[2];  const float* bu = (const float*)d_in[3];
    const float* Wv = (const float*)d_in[4];  const float* bv = (const float*)d_in[5];
    const float* Wl = (const float*)d_in[6];  const float* bl = (const float*)d_in[7];
    const float* Wq = (const float*)d_in[8];  const float* bq = (const float*)d_in[9];
    const float* Wk = (const float*)d_in[10]; const float* bk = (const float*)d_in[11];
    const float* Wvm= (const float*)d_in[12]; const float* bvm= (const float*)d_in[13];
    const float* Wo = (const float*)d_in[14]; const float* bo = (const float*)d_in[15];
    const float* F1 = (const float*)d_in[16]; const float* f1 = (const float*)d_in[17];
    const float* F2 = (const float*)d_in[18]; const float* f2 = (const float*)d_in[19];
    const float* g1 = (const float*)d_in[20]; const float* be1= (const float*)d_in[21];
    const float* g2 = (const float*)d_in[22]; const float* be2= (const float*)d_in[23];
    const float* ng = (const float*)d_in[24]; const float* nb = (const float*)d_in[25];
    const float* Wp = (const float*)d_in[26]; const float* bp = (const float*)d_in[27];

    float* htb = sym(g_htb);
    float* u   = sym(g_u);
    float* v   = sym(g_v);
    float* x   = sym(g_x);
    float* q   = sym(g_q);
    float* k   = sym(g_k);
    float* vv  = sym(g_vv);
    float* attn= sym(g_attn);
    float* tmp = sym(g_tmp);
    float* ffn = sym(g_ffn);
    float* ht  = sym(g_ht);
    float* out = (float*)d_out;

    const float scale = 0.102062072615966f;   // 1/sqrt(96)

    cudaFuncSetAttribute(flash_kernel, cudaFuncAttributeMaxDynamicSharedMemorySize,
                         FLASH_SMEM);

    // 1) span max pooling -> htb [48,768]
    pool_kernel<<<NN_, 256>>>(emb, spans, htb);

    // 2) u = htb@Wu+bu ; v = htb@Wv+bv
    gemm_tc<false,true,false><<<gemm_grid(NN_, DIM, 1), 256>>>(
        htb, Wu, bu, u, NN_, DIM, DIM, DIM, DIM, DIM, 0, 0, 0);
    gemm_tc<false,true,false><<<gemm_grid(NN_, DIM, 1), 256>>>(
        htb, Wv, bv, v, NN_, DIM, DIM, DIM, DIM, DIM, 0, 0, 0);

    // 3) pair = relu(u_i + v_j) ; x = relu(pair @ Wl + bl)
    build_pair_kernel<<<TT, 256>>>(u, v, tmp);
    gemm_tc<false,true,true><<<gemm_grid(TT, DIM, 1), 256>>>(
        tmp, Wl, bl, x, TT, DIM, DIM, DIM, DIM, DIM, 0, 0, 0);

    // 4) MatTransformer layers
    for (int l = 0; l < NLAYER; l++) {
        const float* Wq_l = Wq + (size_t)l * DIM * DIM;  const float* bq_l = bq + (size_t)l * DIM;
        const float* Wk_l = Wk + (size_t)l * DIM * DIM;  const float* bk_l = bk + (size_t)l * DIM;
        const float* Wv_l = Wvm+ (size_t)l * DIM * DIM;  const float* bv_l = bvm+ (size_t)l * DIM;
        const float* Wo_l = Wo + (size_t)l * DIM * DIM;  const float* bo_l = bo + (size_t)l * DIM;
        const float* F1_l = F1 + (size_t)l * DIM * DFF;  const float* f1_l = f1 + (size_t)l * DFF;
        const float* F2_l = F2 + (size_t)l * DFF * DIM;  const float* f2_l = f2 + (size_t)l * DIM;
        const float* g1_l = g1 + (size_t)l * DIM;        const float* be1_l= be1+ (size_t)l * DIM;
        const float* g2_l = g2 + (size_t)l * DIM;        const float* be2_l= be2+ (size_t)l * DIM;

        // QKV projections
        gemm_tc<false,true,false><<<gemm_grid(TT, DIM, 1), 256>>>(
            x, Wq_l, bq_l, q, TT, DIM, DIM, DIM, DIM, DIM, 0, 0, 0);
        gemm_tc<false,true,false><<<gemm_grid(TT, DIM, 1), 256>>>(
            x, Wk_l, bk_l, k, TT, DIM, DIM, DIM, DIM, DIM, 0, 0, 0);
        gemm_tc<false,true,false><<<gemm_grid(TT, DIM, 1), 256>>>(
            x, Wv_l, bv_l, vv, TT, DIM, DIM, DIM, DIM, DIM, 0, 0, 0);

        // fused attention: softmax(QK^T * scale) @ V  -> attn
        flash_kernel<<<dim3(TT / 128, NHEAD), 256, FLASH_SMEM>>>(q, k, vv, attn, scale);

        // output projection + residual LN
        gemm_tc<false,true,false><<<gemm_grid(TT, DIM, 1), 256>>>(
            attn, Wo_l, bo_l, tmp, TT, DIM, DIM, DIM, DIM, DIM, 0, 0, 0);
        add_ln_kernel<<<TT, 256>>>(x, tmp, g1_l, be1_l);

        // FFN + residual LN
        gemm_tc<false,true,true><<<gemm_grid(TT, DFF, 1), 256>>>(
            x, F1_l, f1_l, ffn, TT, DFF, DIM, DIM, DFF, DFF, 0, 0, 0);
        gemm_tc<false,true,false><<<gemm_grid(TT, DIM, 1), 256>>>(
            ffn, F2_l, f2_l, tmp, TT, DIM, DFF, DFF, DIM, DIM, 0, 0, 0);
        add_ln_kernel<<<TT, 256>>>(x, tmp, g2_l, be2_l);
    }

    // 5) final gather + LN + predictor + bag max
    final_kernel<<<BAG, 256>>>(x, ng, nb, Wp, bp, ht);
    writeout_kernel<<<1, 128>>>(ht, out, out_size);
}